// round 16
// baseline (speedup 1.0000x reference)
#include <cuda_runtime.h>
#include <math.h>

// Problem dims
#define MB     256
#define RDIM   1025
#define CDIM   1024
#define NSPLIT 8
#define BT     8
#define NE     (MB * NSPLIT)                // 2048 E-stream blocks (first)
#define NGEMM  ((MB / BT) * (CDIM / 256))   // 128 GEMM blocks (last)
#define TARGET (NSPLIT + 4)                 // writers per batch-row b per call

// Scratch (__device__ globals: allocation-free)
static __device__ float g_part[MB * NSPLIT * CDIM];
static __device__ float g_gemm[MB * CDIM];
static __device__ float g_red[4];
static __device__ unsigned int g_cnt[MB];   // monotonic, never reset
static __device__ unsigned int g_cnt2;      // dkl writers counter

// h[b, o..o+3] = gemm + exp(0.5*lv_out)*sum_chunks(part)
__device__ __forceinline__ void write_h(int b, int tid,
                                        const float* __restrict__ lv_out,
                                        float* __restrict__ out)
{
    const int o = tid << 2;
    float4 s = make_float4(0.f, 0.f, 0.f, 0.f);
    #pragma unroll
    for (int c = 0; c < NSPLIT; ++c) {
        float4 p = *(const float4*)(g_part + ((b * NSPLIT + c) * CDIM) + o);
        s.x += p.x; s.y += p.y; s.z += p.z; s.w += p.w;
    }
    float4 gm = *(const float4*)(g_gemm + b * CDIM + o);
    float4 lv = *(const float4*)(lv_out + o);
    float4 r;
    r.x = gm.x + __expf(0.5f * lv.x) * s.x;
    r.y = gm.y + __expf(0.5f * lv.y) * s.y;
    r.z = gm.z + __expf(0.5f * lv.z) * s.z;
    r.w = gm.w + __expf(0.5f * lv.w) * s.w;
    *(float4*)(out + b * CDIM + o) = r;
}

// -------------------------------------------------------------------------
// Single fused kernel, 8 CTAs/SM.
//   blocks [0, NE):        E-stream role (2-row double-buffered LDG.128)
//   blocks [NE, NE+NGEMM): GEMM role (BT=8) + mu^2 partials + dkl finalize
//   last of the 12 writers touching batch-row b emits h[b,:].
// -------------------------------------------------------------------------
__global__ __launch_bounds__(256, 8) void k_all(const float* __restrict__ E,
                                                const float* __restrict__ mu,
                                                const float* __restrict__ x,
                                                const float* __restrict__ lv_in,
                                                const float* __restrict__ lv_out,
                                                float* __restrict__ out)
{
    __shared__ __align__(16) float sm[1024];   // 4 KB, role-dependent use
    __shared__ unsigned int s_mask;
    __shared__ unsigned int s_flag;
    const int tid = threadIdx.x;
    const int bid = blockIdx.x;

    if (bid < NE) {
        // ================= E-stream role =================
        const int b     = bid >> 3;
        const int chunk = bid & 7;
        const int i0 = (chunk * RDIM) / NSPLIT;
        const int i1 = ((chunk + 1) * RDIM) / NSPLIT;
        const int n  = i1 - i0;                       // 128 or 129

        // a[i] = x1[b,i0+i] * exp(0.5*lv_in[i0+i])
        #pragma unroll 1
        for (int idx = tid; idx < n; idx += 256) {
            int gi = i0 + idx;
            float xv = (gi < CDIM) ? x[b * CDIM + gi] : 1.0f;
            sm[idx] = xv * __expf(0.5f * lv_in[gi]);
        }
        __syncthreads();

        const float4* __restrict__ Ep =
            (const float4*)(E + (long long)b * (RDIM * CDIM)
                              + (long long)i0 * CDIM) + tid;

        float4 c0 = make_float4(0.f, 0.f, 0.f, 0.f);
        float4 c1 = c0;

        const int m = n & ~1;          // even part
        if (n & 1) {                   // peel the odd last row
            float4 e = __ldcs(Ep + m * 256);
            float a = sm[m];
            c0.x += a * e.x; c0.y += a * e.y; c0.z += a * e.z; c0.w += a * e.w;
        }

        // 2-row double-buffered stream over m rows
        float4 e0 = __ldcs(Ep);
        float4 e1 = __ldcs(Ep + 256);
        int i = 0;
        #pragma unroll 1
        for (; i + 2 < m; i += 2) {
            const float4* En = Ep + 512;
            float4 f0 = __ldcs(En);          // next pair in flight
            float4 f1 = __ldcs(En + 256);
            float a0 = sm[i], a1 = sm[i + 1];
            c0.x += a0*e0.x; c0.y += a0*e0.y; c0.z += a0*e0.z; c0.w += a0*e0.w;
            c1.x += a1*e1.x; c1.y += a1*e1.y; c1.z += a1*e1.z; c1.w += a1*e1.w;
            e0 = f0; e1 = f1; Ep = En;
        }
        {   // last buffered pair
            float a0 = sm[i], a1 = sm[i + 1];
            c0.x += a0*e0.x; c0.y += a0*e0.y; c0.z += a0*e0.z; c0.w += a0*e0.w;
            c1.x += a1*e1.x; c1.y += a1*e1.y; c1.z += a1*e1.z; c1.w += a1*e1.w;
        }

        float4 r;
        r.x = c0.x + c1.x; r.y = c0.y + c1.y;
        r.z = c0.z + c1.z; r.w = c0.w + c1.w;
        *(float4*)(g_part + (long long)bid * CDIM + (tid << 2)) = r;

        // publish + count; last of 12 writers emits h[b,:]
        __threadfence();
        __syncthreads();
        if (tid == 0) {
            unsigned int old = atomicAdd(&g_cnt[b], 1u);
            s_flag = ((old + 1u) % TARGET == 0u) ? 1u : 0u;
        }
        __syncthreads();
        if (s_flag) {
            __threadfence();
            write_h(b, tid, lv_out, out);
        }
    } else {
        // ================= GEMM role (BT = 8) =================
        const int g  = bid - NE;            // 0..127
        const int bt = g >> 2;              // 0..31
        const int ot = g & 3;               // 0..3
        const int b0 = bt * BT;
        const int o  = ot * 256 + tid;

        float acc[BT];
        #pragma unroll
        for (int k = 0; k < BT; ++k) acc[k] = 0.f;
        float musq = 0.f;

        #pragma unroll 1
        for (int ic = 0; ic < RDIM; ic += 128) {
            const int len = min(128, RDIM - ic);
            // xsm[il*8 + bl] = x1[b0+bl, ic+il]
            #pragma unroll 1
            for (int idx = tid; idx < len * BT; idx += 256) {
                int il = idx >> 3;
                int bl = idx & 7;
                int gi = ic + il;
                sm[idx] = (gi < CDIM) ? x[(b0 + bl) * CDIM + gi] : 1.0f;
            }
            __syncthreads();

            int il = 0;
            #pragma unroll 1
            for (; il + 4 <= len; il += 4) {
                float mv0 = mu[(ic + il    ) * CDIM + o];
                float mv1 = mu[(ic + il + 1) * CDIM + o];
                float mv2 = mu[(ic + il + 2) * CDIM + o];
                float mv3 = mu[(ic + il + 3) * CDIM + o];
                musq += mv0*mv0 + mv1*mv1 + mv2*mv2 + mv3*mv3;
                #pragma unroll
                for (int r = 0; r < 4; ++r) {
                    float mv = (r == 0) ? mv0 : (r == 1) ? mv1 : (r == 2) ? mv2 : mv3;
                    const float4* xp = (const float4*)(sm + ((il + r) << 3));
                    float4 x0 = xp[0], x1v = xp[1];
                    acc[0] += x0.x  * mv; acc[1] += x0.y  * mv;
                    acc[2] += x0.z  * mv; acc[3] += x0.w  * mv;
                    acc[4] += x1v.x * mv; acc[5] += x1v.y * mv;
                    acc[6] += x1v.z * mv; acc[7] += x1v.w * mv;
                }
            }
            #pragma unroll 1
            for (; il < len; ++il) {
                float mv = mu[(ic + il) * CDIM + o];
                musq += mv * mv;
                const float4* xp = (const float4*)(sm + (il << 3));
                float4 x0 = xp[0], x1v = xp[1];
                acc[0] += x0.x  * mv; acc[1] += x0.y  * mv;
                acc[2] += x0.z  * mv; acc[3] += x0.w  * mv;
                acc[4] += x1v.x * mv; acc[5] += x1v.y * mv;
                acc[6] += x1v.z * mv; acc[7] += x1v.w * mv;
            }
            __syncthreads();
        }
        #pragma unroll
        for (int k = 0; k < BT; ++k)
            g_gemm[(b0 + k) * CDIM + o] = acc[k];

        // mu^2 partial (bt==0 blocks cover mu exactly once)
        if (bt == 0) {
            for (int off = 16; off; off >>= 1)
                musq += __shfl_down_sync(0xffffffffu, musq, off);
            __syncthreads();
            if ((tid & 31) == 0) sm[tid >> 5] = musq;
            __syncthreads();
            if (tid == 0) {
                float v = 0.f;
                #pragma unroll
                for (int w = 0; w < 8; ++w) v += sm[w];
                g_red[ot] = v;
            }
        }

        // publish + count the 8 batch rows this block completed
        __threadfence();
        __syncthreads();
        if (tid == 0) {
            unsigned int m = 0;
            #pragma unroll
            for (int k = 0; k < BT; ++k) {
                unsigned int old = atomicAdd(&g_cnt[b0 + k], 1u);
                if ((old + 1u) % TARGET == 0u) m |= (1u << k);
            }
            s_mask = m;
        }
        __syncthreads();
        {
            unsigned int m = s_mask;
            if (m) {
                __threadfence();
                #pragma unroll 1
                for (int k = 0; k < BT; ++k)
                    if ((m >> k) & 1u) write_h(b0 + k, tid, lv_out, out);
            }
        }

        // D_KL: last of the 4 bt==0 blocks finalizes
        if (bt == 0) {
            if (tid == 0) {
                unsigned int old2 = atomicAdd(&g_cnt2, 1u);
                s_flag = (((old2 + 1u) & 3u) == 0u) ? 1u : 0u;
            }
            __syncthreads();
            if (s_flag) {
                __threadfence();
                float svr = 0.f, slvi = 0.f, svc = 0.f, slvo = 0.f;
                for (int i = tid; i < RDIM; i += 256) {
                    float v = lv_in[i];
                    svr  += __expf(v);
                    slvi += v;
                }
                for (int i = tid; i < CDIM; i += 256) {
                    float v = lv_out[i];
                    svc  += __expf(v);
                    slvo += v;
                }
                float vals[4] = {svr, slvi, svc, slvo};
                __syncthreads();
                #pragma unroll
                for (int k = 0; k < 4; ++k) {
                    float v = vals[k];
                    for (int off = 16; off; off >>= 1)
                        v += __shfl_down_sync(0xffffffffu, v, off);
                    if ((tid & 31) == 0) sm[k * 8 + (tid >> 5)] = v;
                }
                __syncthreads();
                if (tid == 0) {
                    float tot[4];
                    #pragma unroll
                    for (int k = 0; k < 4; ++k) {
                        float v = 0.f;
                        #pragma unroll
                        for (int w = 0; w < 8; ++w) v += sm[k * 8 + w];
                        tot[k] = v;
                    }
                    float musq_t = g_red[0] + g_red[1] + g_red[2] + g_red[3];
                    float dkl = 0.5f * (tot[0] * tot[2] + musq_t
                                        - (float)RDIM * (float)CDIM
                                        - (float)CDIM * tot[1]
                                        - (float)RDIM * tot[3]);
                    out[MB * CDIM] = dkl;
                }
            }
        }
    }
}

// -------------------------------------------------------------------------
extern "C" void kernel_launch(void* const* d_in, const int* in_sizes, int n_in,
                              void* d_out, int out_size)
{
    const float* x      = (const float*)d_in[0];   // (256, 1024)
    const float* mu     = (const float*)d_in[1];   // (1025, 1024)
    const float* lv_in  = (const float*)d_in[2];   // (1025,)
    const float* lv_out = (const float*)d_in[3];   // (1024,)
    const float* E      = (const float*)d_in[4];   // (256, 1025, 1024)
    float* out = (float*)d_out;                    // (256*1024 h) + 1 scalar

    k_all<<<NE + NGEMM, 256>>>(E, mu, x, lv_in, lv_out, out);
}